// round 3
// baseline (speedup 1.0000x reference)
#include <cuda_runtime.h>
#include <math.h>

#define NPTS 4096
#define BATCH 4
#define CCH 128
#define KNN 10
#define RTOT (BATCH * NPTS)

// ---------------- scratch (device globals) ----------------
__device__ float g_Wc1[256 * 128];
__device__ float g_Wc2[512 * 128];
__device__ float g_xcat[BATCH * 512 * NPTS];   // channel-major [b][512][N]
__device__ float g_UV1[RTOT * 256];            // channel-major [b][256][N]
__device__ float g_UV1t[RTOT * 256];           // point-major  [b][N][256]
__device__ float g_UV2[RTOT * 512];
__device__ float g_UV2t[RTOT * 512];
__device__ float g_xt[RTOT * 256];             // point-major stage output (max C=256)
__device__ float g_y3[RTOT * 128];
__device__ int   g_idx[RTOT * KNN];
__device__ float g_kpd[BATCH * 4 * NPTS * KNN];
__device__ int   g_kpi[BATCH * 4 * NPTS * KNN];
__device__ float g_psum[BATCH * 1024 * 256];
__device__ float g_pssq[BATCH * 1024 * 256];
__device__ float g_mu[BATCH * 256];
__device__ float g_rstd[BATCH * 256];

// ---------------- weight prep ----------------
__global__ void prep_w(const float* __restrict__ W1, const float* __restrict__ W2,
                       float* __restrict__ Wc1, float* __restrict__ Wc2) {
    int i = blockIdx.x * blockDim.x + threadIdx.x;
    if (i < 256 * 128) {
        int o = i / 128, c = i % 128;
        if (o < 128) Wc1[i] = W1[o * 256 + c] - W1[o * 256 + 128 + c];
        else         Wc1[i] = W1[(o - 128) * 256 + 128 + c];
    }
    if (i < 512 * 128) {
        int o = i / 128, c = i % 128;
        if (o < 256) Wc2[i] = W2[o * 256 + c] - W2[o * 256 + 128 + c];
        else         Wc2[i] = W2[(o - 256) * 256 + 128 + c];
    }
}

// ---------------- copy x0 (features) into xcat rows [0,128) ----------------
__global__ void copy_x0(const float4* __restrict__ f, float4* __restrict__ xcat) {
    int i = blockIdx.x * blockDim.x + threadIdx.x;
    const int per = CCH * NPTS / 4;
    if (i >= BATCH * per) return;
    int b = i / per, r = i % per;
    xcat[(size_t)b * (512 * NPTS / 4) + r] = f[i];
}

// ---------------- KNN pass1: per-slice top-10 ----------------
__global__ void knn_part(const float* __restrict__ coords,
                         float* __restrict__ pd, int* __restrict__ pi) {
    int b = blockIdx.z, s = blockIdx.y;
    int n = blockIdx.x * 256 + threadIdx.x;
    const float* cb = coords + (size_t)b * 3 * NPTS;
    __shared__ float sx[1024], sy[1024], sz[1024], ss[1024];
    int base = s * 1024;
    for (int j = threadIdx.x; j < 1024; j += 256) {
        float x = cb[base + j], y = cb[NPTS + base + j], z = cb[2 * NPTS + base + j];
        sx[j] = x; sy[j] = y; sz[j] = z; ss[j] = x * x + y * y + z * z;
    }
    __syncthreads();
    float qx = cb[n], qy = cb[NPTS + n], qz = cb[2 * NPTS + n];
    float qs = qx * qx + qy * qy + qz * qz;
    float dist[KNN]; int ind[KNN];
#pragma unroll
    for (int i = 0; i < KNN; i++) { dist[i] = 3.4e38f; ind[i] = 0x7fffffff; }
    float worst = 3.4e38f;
    for (int j = 0; j < 1024; j++) {
        int jj = base + j;
        float d = qs + ss[j] - 2.f * (qx * sx[j] + qy * sy[j] + qz * sz[j]);
        d = fmaxf(d, 1e-12f);
        if (d < worst && jj != n) {
            int p = KNN - 1;
            while (p > 0 && dist[p - 1] > d) { dist[p] = dist[p - 1]; ind[p] = ind[p - 1]; p--; }
            dist[p] = d; ind[p] = jj;
            worst = dist[KNN - 1];
        }
    }
    size_t off = ((size_t)(b * 4 + s) * NPTS + n) * KNN;
#pragma unroll
    for (int i = 0; i < KNN; i++) { pd[off + i] = dist[i]; pi[off + i] = ind[i]; }
}

// ---------------- KNN merge: 4 sorted lists -> final 10 ----------------
__global__ void knn_merge(const float* __restrict__ pd, const int* __restrict__ pi,
                          int* __restrict__ out) {
    int t = blockIdx.x * 256 + threadIdx.x;
    if (t >= RTOT) return;
    int b = t >> 12, n = t & (NPTS - 1);
    const float* pdp[4]; const int* pip[4]; int pos[4] = {0, 0, 0, 0};
#pragma unroll
    for (int s = 0; s < 4; s++) {
        size_t off = ((size_t)(b * 4 + s) * NPTS + n) * KNN;
        pdp[s] = pd + off; pip[s] = pi + off;
    }
    int* op = out + (size_t)t * KNN;
#pragma unroll
    for (int r = 0; r < KNN; r++) {
        float best = 3.5e38f; int bs = 0, bidx = 0x7fffffff;
#pragma unroll
        for (int s = 0; s < 4; s++) {
            float dv = pdp[s][pos[s]];
            int iv = pip[s][pos[s]];
            if (dv < best || (dv == best && iv < bidx)) { best = dv; bs = s; bidx = iv; }
        }
        op[r] = bidx; pos[bs]++;
    }
}

// ---------------- fp32 tiled GEMM (R1, measured-good): O[b] = A (MxK) * X[b] (K x N) ----
__global__ void gemm_kernel(const float* __restrict__ A, const float* __restrict__ X,
                            float* __restrict__ O, int Kd,
                            size_t strideX, size_t strideO) {
    const int NN = NPTS;
    int b = blockIdx.z;
    const float* Xb = X + (size_t)b * strideX;
    float* Ob = O + (size_t)b * strideO;
    int n0 = blockIdx.x * 64, m0 = blockIdx.y * 64;

    __shared__ float As[16][68];
    __shared__ float Xs[16][64];

    int tid = threadIdx.x;
    int tn = (tid & 15) * 4;
    int tm = (tid >> 4) * 4;
    float acc[4][4] = {};

    for (int k0 = 0; k0 < Kd; k0 += 16) {
        {
            int mm = tid >> 2;
            int kk = (tid & 3) * 4;
            float4 v = *(const float4*)&A[(size_t)(m0 + mm) * Kd + k0 + kk];
            As[kk + 0][mm] = v.x; As[kk + 1][mm] = v.y;
            As[kk + 2][mm] = v.z; As[kk + 3][mm] = v.w;
        }
        {
            int kk = tid >> 4;
            int nn = (tid & 15) * 4;
            *(float4*)&Xs[kk][nn] =
                *(const float4*)&Xb[(size_t)(k0 + kk) * NN + n0 + nn];
        }
        __syncthreads();
#pragma unroll
        for (int kk = 0; kk < 16; kk++) {
            float4 a = *(const float4*)&As[kk][tm];
            float4 x = *(const float4*)&Xs[kk][tn];
            float av[4] = {a.x, a.y, a.z, a.w};
            float xv[4] = {x.x, x.y, x.z, x.w};
#pragma unroll
            for (int i = 0; i < 4; i++)
#pragma unroll
                for (int j = 0; j < 4; j++)
                    acc[i][j] += av[i] * xv[j];
        }
        __syncthreads();
    }
#pragma unroll
    for (int i = 0; i < 4; i++) {
        float4 v = make_float4(acc[i][0], acc[i][1], acc[i][2], acc[i][3]);
        *(float4*)&Ob[(size_t)(m0 + tm + i) * NN + n0 + tn] = v;
    }
}

// ---------------- transpose channel-major -> point-major: [b][R][N] -> [b][N][R] -----
__global__ void t_c2p(const float* __restrict__ in, float* __restrict__ out, int R) {
    __shared__ float sm[32][33];
    int b = blockIdx.z, n0 = blockIdx.x * 32, r0 = blockIdx.y * 32;
    int tx = threadIdx.x, ty = threadIdx.y;
#pragma unroll
    for (int q = 0; q < 4; q++)   // sm[r_local][n_local]
        sm[ty + q * 8][tx] = in[((size_t)b * R + r0 + ty + q * 8) * NPTS + n0 + tx];
    __syncthreads();
#pragma unroll
    for (int q = 0; q < 4; q++) {
        int n = n0 + ty + q * 8;
        out[((size_t)(b * NPTS + n)) * R + r0 + tx] = sm[tx][ty + q * 8];
    }
}

// ---------------- EdgeConv gather + max_k + stats partials (point-major) --------------
// UVt [b][N][2C] (U cols 0..C-1, V cols C..2C-1) -> xt [b][N][C] unnormalized max.
template <int C>
__global__ void edge_kernel(const float* __restrict__ UVt, const int* __restrict__ idx,
                            float* __restrict__ xt,
                            float* __restrict__ psum, float* __restrict__ pssq) {
    const int RS = 2 * C;
    const int J = C / 128;
    int b = blockIdx.y;
    int warp = threadIdx.x >> 5, lane = threadIdx.x & 31;
    int qbase = blockIdx.x * 32 + warp * 4;
    const float* UVb = UVt + (size_t)b * NPTS * RS;
    const int* idb = idx + (size_t)b * NPTS * KNN;

    float sum[4 * J], ssq[4 * J];
#pragma unroll
    for (int e = 0; e < 4 * J; e++) { sum[e] = 0.f; ssq[e] = 0.f; }

    for (int i = 0; i < 4; i++) {
        int q = qbase + i;
        const float* urow = UVb + (size_t)q * RS;
        float4 u[J], m[J];
#pragma unroll
        for (int j = 0; j < J; j++) {
            u[j] = *(const float4*)&urow[j * 128 + 4 * lane];
            m[j] = make_float4(-3.4e38f, -3.4e38f, -3.4e38f, -3.4e38f);
        }
        int jn[KNN];
#pragma unroll
        for (int kk = 0; kk < KNN; kk++) jn[kk] = idb[q * KNN + kk];
#pragma unroll
        for (int kk = 0; kk < KNN; kk++) {
            const float* vrow = UVb + (size_t)jn[kk] * RS + C;
#pragma unroll
            for (int j = 0; j < J; j++) {
                float4 v = *(const float4*)&vrow[j * 128 + 4 * lane];
                float y0 = u[j].x + v.x, y1 = u[j].y + v.y;
                float y2 = u[j].z + v.z, y3 = u[j].w + v.w;
                m[j].x = fmaxf(m[j].x, y0); m[j].y = fmaxf(m[j].y, y1);
                m[j].z = fmaxf(m[j].z, y2); m[j].w = fmaxf(m[j].w, y3);
                sum[j * 4 + 0] += y0; ssq[j * 4 + 0] += y0 * y0;
                sum[j * 4 + 1] += y1; ssq[j * 4 + 1] += y1 * y1;
                sum[j * 4 + 2] += y2; ssq[j * 4 + 2] += y2 * y2;
                sum[j * 4 + 3] += y3; ssq[j * 4 + 3] += y3 * y3;
            }
        }
        float* orow = xt + (size_t)(b * NPTS + q) * C;
#pragma unroll
        for (int j = 0; j < J; j++)
            *(float4*)&orow[j * 128 + 4 * lane] = m[j];
    }
    int w = blockIdx.x * 8 + warp;   // 0..1023
    float* ps = psum + (size_t)(b * 1024 + w) * 256;
    float* pq = pssq + (size_t)(b * 1024 + w) * 256;
#pragma unroll
    for (int j = 0; j < J; j++) {
        *(float4*)&ps[j * 128 + 4 * lane] = make_float4(sum[j * 4], sum[j * 4 + 1], sum[j * 4 + 2], sum[j * 4 + 3]);
        *(float4*)&pq[j * 128 + 4 * lane] = make_float4(ssq[j * 4], ssq[j * 4 + 1], ssq[j * 4 + 2], ssq[j * 4 + 3]);
    }
}

// ---------------- reduce partials -> mu, rstd (deterministic, double) ----------------
__global__ void reduce_stats(const float* __restrict__ psum, const float* __restrict__ pssq,
                             float* __restrict__ mu, float* __restrict__ rstd, double cnt) {
    int o = blockIdx.x, b = blockIdx.y, t = threadIdx.x;
    __shared__ double sr[128], sr2[128];
    double s = 0.0, s2 = 0.0;
    for (int w = t; w < 1024; w += 128) {
        s  += (double)psum[(size_t)(b * 1024 + w) * 256 + o];
        s2 += (double)pssq[(size_t)(b * 1024 + w) * 256 + o];
    }
    sr[t] = s; sr2[t] = s2;
    __syncthreads();
    for (int st = 64; st > 0; st >>= 1) {
        if (t < st) { sr[t] += sr[t + st]; sr2[t] += sr2[t + st]; }
        __syncthreads();
    }
    if (t == 0) {
        double m = sr[0] / cnt;
        double var = sr2[0] / cnt - m * m;
        mu[b * 256 + o] = (float)m;
        rstd[b * 256 + o] = (float)(1.0 / sqrt(var + 1e-5));
    }
}

// ----- normalize + lrelu + transpose point-major xt[b][N][C] -> xcat rows [outRow0..) -----
__global__ void norm_t_p2c(const float* __restrict__ xt, int C,
                           const float* __restrict__ mu, const float* __restrict__ rstd,
                           float* __restrict__ xcat, int outRow0) {
    __shared__ float sm[32][33];
    int b = blockIdx.z, n0 = blockIdx.x * 32, c0 = blockIdx.y * 32;
    int tx = threadIdx.x, ty = threadIdx.y;
#pragma unroll
    for (int q = 0; q < 4; q++) {   // sm[n_local][c_local]
        int n = n0 + ty + q * 8;
        sm[ty + q * 8][tx] = xt[((size_t)(b * NPTS + n)) * C + c0 + tx];
    }
    __syncthreads();
#pragma unroll
    for (int q = 0; q < 4; q++) {
        int c = c0 + ty + q * 8;
        float m = mu[b * 256 + c], r = rstd[b * 256 + c];
        float v = (sm[tx][ty + q * 8] - m) * r;
        v = v >= 0.f ? v : 0.2f * v;
        xcat[((size_t)b * 512 + outRow0 + c) * NPTS + n0 + tx] = v;
    }
}

// ---------------- final instance-norm (over N) + lrelu, channel-major ----------------
__global__ void norm_epilogue(const float* __restrict__ Y, float* __restrict__ out) {
    int o = blockIdx.x, b = blockIdx.y, tid = threadIdx.x;
    const float* y = Y + ((size_t)b * CCH + o) * NPTS;
    float* op = out + ((size_t)b * CCH + o) * NPTS;

    __shared__ double sred[256], s2red[256];
    __shared__ float  smu, srstd;

    double s = 0.0, s2 = 0.0;
    for (int n = tid; n < NPTS; n += 256) {
        float v = y[n];
        s += (double)v; s2 += (double)v * (double)v;
    }
    sred[tid] = s; s2red[tid] = s2;
    __syncthreads();
    for (int st = 128; st > 0; st >>= 1) {
        if (tid < st) { sred[tid] += sred[tid + st]; s2red[tid] += s2red[tid + st]; }
        __syncthreads();
    }
    if (tid == 0) {
        double cnt = (double)NPTS;
        double m  = sred[0] / cnt;
        double var = s2red[0] / cnt - m * m;
        smu   = (float)m;
        srstd = (float)(1.0 / sqrt(var + 1e-5));
    }
    __syncthreads();
    float m = smu, r = srstd;
    for (int n = tid; n < NPTS; n += 256) {
        float v = (y[n] - m) * r;
        op[n] = v >= 0.f ? v : 0.2f * v;
    }
}

// ---------------- launch ----------------
extern "C" void kernel_launch(void* const* d_in, const int* in_sizes, int n_in,
                              void* d_out, int out_size) {
    const float* coords = (const float*)d_in[0];
    const float* feats  = (const float*)d_in[1];
    const float* W1     = (const float*)d_in[2];
    const float* W2     = (const float*)d_in[3];
    const float* W3     = (const float*)d_in[4];
    float* out = (float*)d_out;

    float *Wc1, *Wc2, *xcat, *UV1, *UV1t, *UV2, *UV2t, *xt, *y3, *kpd, *psum, *pssq, *mu, *rstd;
    int *idx, *kpi;
    cudaGetSymbolAddress((void**)&Wc1,  g_Wc1);
    cudaGetSymbolAddress((void**)&Wc2,  g_Wc2);
    cudaGetSymbolAddress((void**)&xcat, g_xcat);
    cudaGetSymbolAddress((void**)&UV1,  g_UV1);
    cudaGetSymbolAddress((void**)&UV1t, g_UV1t);
    cudaGetSymbolAddress((void**)&UV2,  g_UV2);
    cudaGetSymbolAddress((void**)&UV2t, g_UV2t);
    cudaGetSymbolAddress((void**)&xt,   g_xt);
    cudaGetSymbolAddress((void**)&y3,   g_y3);
    cudaGetSymbolAddress((void**)&idx,  g_idx);
    cudaGetSymbolAddress((void**)&kpd,  g_kpd);
    cudaGetSymbolAddress((void**)&kpi,  g_kpi);
    cudaGetSymbolAddress((void**)&psum, g_psum);
    cudaGetSymbolAddress((void**)&pssq, g_pssq);
    cudaGetSymbolAddress((void**)&mu,   g_mu);
    cudaGetSymbolAddress((void**)&rstd, g_rstd);

    prep_w<<<256, 256>>>(W1, W2, Wc1, Wc2);
    copy_x0<<<(BATCH * CCH * NPTS / 4 + 255) / 256, 256>>>((const float4*)feats, (float4*)xcat);
    knn_part<<<dim3(NPTS / 256, 4, BATCH), 256>>>(coords, kpd, kpi);
    knn_merge<<<RTOT / 256, 256>>>(kpd, kpi, idx);

    // stage 1: UV1 = Wc1 @ x0   (channel-major GEMM), then transpose, gather, norm back
    gemm_kernel<<<dim3(NPTS / 64, 256 / 64, BATCH), 256>>>(
        Wc1, xcat, UV1, 128, (size_t)512 * NPTS, (size_t)256 * NPTS);
    t_c2p<<<dim3(NPTS / 32, 256 / 32, BATCH), dim3(32, 8)>>>(UV1, UV1t, 256);
    edge_kernel<128><<<dim3(NPTS / 32, BATCH), 256>>>(UV1t, idx, xt, psum, pssq);
    reduce_stats<<<dim3(128, BATCH), 128>>>(psum, pssq, mu, rstd, (double)NPTS * KNN);
    norm_t_p2c<<<dim3(NPTS / 32, 128 / 32, BATCH), dim3(32, 8)>>>(xt, 128, mu, rstd, xcat, 128);

    // stage 2
    gemm_kernel<<<dim3(NPTS / 64, 512 / 64, BATCH), 256>>>(
        Wc2, xcat + (size_t)128 * NPTS, UV2, 128, (size_t)512 * NPTS, (size_t)512 * NPTS);
    t_c2p<<<dim3(NPTS / 32, 512 / 32, BATCH), dim3(32, 8)>>>(UV2, UV2t, 512);
    edge_kernel<256><<<dim3(NPTS / 32, BATCH), 256>>>(UV2t, idx, xt, psum, pssq);
    reduce_stats<<<dim3(256, BATCH), 128>>>(psum, pssq, mu, rstd, (double)NPTS * KNN);
    norm_t_p2c<<<dim3(NPTS / 32, 256 / 32, BATCH), dim3(32, 8)>>>(xt, 256, mu, rstd, xcat, 256);

    // stage 3
    gemm_kernel<<<dim3(NPTS / 64, 128 / 64, BATCH), 256>>>(
        W3, xcat, y3, 512, (size_t)512 * NPTS, (size_t)128 * NPTS);
    norm_epilogue<<<dim3(128, BATCH), 256>>>(y3, out);
}

// round 4
// speedup vs baseline: 1.0503x; 1.0503x over previous
#include <cuda_runtime.h>
#include <math.h>

#define NPTS 4096
#define BATCH 4
#define CCH 128
#define KNN 10
#define RTOT (BATCH * NPTS)

// ---------------- scratch (device globals) ----------------
__device__ float g_Wc1[256 * 128];
__device__ float g_Wc2[512 * 128];
__device__ float g_UV1[BATCH * 256 * NPTS];
__device__ float g_UV2[BATCH * 512 * NPTS];
__device__ float g_xcat[BATCH * 512 * NPTS];
__device__ float g_y3[BATCH * CCH * NPTS];
__device__ int   g_idt[BATCH * KNN * NPTS];        // transposed: [b][k][n]
__device__ float g_kpd[BATCH * 4 * NPTS * KNN];
__device__ int   g_kpi[BATCH * 4 * NPTS * KNN];

// ---------------- weight prep ----------------
__global__ void prep_w(const float* __restrict__ W1, const float* __restrict__ W2,
                       float* __restrict__ Wc1, float* __restrict__ Wc2) {
    int i = blockIdx.x * blockDim.x + threadIdx.x;
    if (i < 256 * 128) {
        int o = i / 128, c = i % 128;
        if (o < 128) Wc1[i] = W1[o * 256 + c] - W1[o * 256 + 128 + c];
        else         Wc1[i] = W1[(o - 128) * 256 + 128 + c];
    }
    if (i < 512 * 128) {
        int o = i / 128, c = i % 128;
        if (o < 256) Wc2[i] = W2[o * 256 + c] - W2[o * 256 + 128 + c];
        else         Wc2[i] = W2[(o - 256) * 256 + 128 + c];
    }
}

// ---------------- copy x0 into xcat rows [0,128) ----------------
__global__ void copy_x0(const float4* __restrict__ f, float4* __restrict__ xcat) {
    int i = blockIdx.x * blockDim.x + threadIdx.x;
    const int per = CCH * NPTS / 4;
    if (i >= BATCH * per) return;
    int b = i / per, r = i % per;
    xcat[(size_t)b * (512 * NPTS / 4) + r] = f[i];
}

// ---------------- KNN pass1: per-1024-slice top-10 ----------------
__global__ void knn_part(const float* __restrict__ coords,
                         float* __restrict__ pd, int* __restrict__ pi) {
    int b = blockIdx.z, s = blockIdx.y;
    int n = blockIdx.x * 256 + threadIdx.x;
    const float* cb = coords + (size_t)b * 3 * NPTS;
    __shared__ float sx[1024], sy[1024], sz[1024], ss[1024];
    int base = s * 1024;
    for (int j = threadIdx.x; j < 1024; j += 256) {
        float x = cb[base + j], y = cb[NPTS + base + j], z = cb[2 * NPTS + base + j];
        sx[j] = x; sy[j] = y; sz[j] = z; ss[j] = x * x + y * y + z * z;
    }
    __syncthreads();
    float qx = cb[n], qy = cb[NPTS + n], qz = cb[2 * NPTS + n];
    float qs = qx * qx + qy * qy + qz * qz;
    float dist[KNN]; int ind[KNN];
#pragma unroll
    for (int i = 0; i < KNN; i++) { dist[i] = 3.4e38f; ind[i] = 0x7fffffff; }
    float worst = 3.4e38f;
    for (int j = 0; j < 1024; j++) {
        int jj = base + j;
        float d = qs + ss[j] - 2.f * (qx * sx[j] + qy * sy[j] + qz * sz[j]);
        d = fmaxf(d, 1e-12f);
        if (d < worst && jj != n) {
            int p = KNN - 1;
            while (p > 0 && dist[p - 1] > d) { dist[p] = dist[p - 1]; ind[p] = ind[p - 1]; p--; }
            dist[p] = d; ind[p] = jj;
            worst = dist[KNN - 1];
        }
    }
    size_t off = ((size_t)(b * 4 + s) * NPTS + n) * KNN;
#pragma unroll
    for (int i = 0; i < KNN; i++) { pd[off + i] = dist[i]; pi[off + i] = ind[i]; }
}

// ---------------- KNN merge: 4 sorted lists -> final 10, TRANSPOSED output ----------------
__global__ void knn_merge(const float* __restrict__ pd, const int* __restrict__ pi,
                          int* __restrict__ idt) {
    int t = blockIdx.x * 256 + threadIdx.x;
    if (t >= RTOT) return;
    int b = t >> 12, n = t & (NPTS - 1);
    const float* pdp[4]; const int* pip[4]; int pos[4] = {0, 0, 0, 0};
#pragma unroll
    for (int s = 0; s < 4; s++) {
        size_t off = ((size_t)(b * 4 + s) * NPTS + n) * KNN;
        pdp[s] = pd + off; pip[s] = pi + off;
    }
#pragma unroll
    for (int r = 0; r < KNN; r++) {
        float best = 3.5e38f; int bs = 0, bidx = 0x7fffffff;
#pragma unroll
        for (int s = 0; s < 4; s++) {
            float dv = pdp[s][pos[s]];
            int iv = pip[s][pos[s]];
            if (dv < best || (dv == best && iv < bidx)) { best = dv; bs = s; bidx = iv; }
        }
        idt[((size_t)b * KNN + r) * NPTS + n] = bidx;   // coalesced per r
        pos[bs]++;
    }
}

// ---------------- fp32 tiled GEMM (R1 verbatim): O[b] = A (MxK) * X[b] (K x N) ----------
__global__ void gemm_kernel(const float* __restrict__ A, const float* __restrict__ X,
                            float* __restrict__ O, int Kd,
                            size_t strideX, size_t strideO) {
    const int NN = NPTS;
    int b = blockIdx.z;
    const float* Xb = X + (size_t)b * strideX;
    float* Ob = O + (size_t)b * strideO;
    int n0 = blockIdx.x * 64, m0 = blockIdx.y * 64;

    __shared__ float As[16][68];
    __shared__ float Xs[16][64];

    int tid = threadIdx.x;
    int tn = (tid & 15) * 4;
    int tm = (tid >> 4) * 4;
    float acc[4][4] = {};

    for (int k0 = 0; k0 < Kd; k0 += 16) {
        {
            int mm = tid >> 2;
            int kk = (tid & 3) * 4;
            float4 v = *(const float4*)&A[(size_t)(m0 + mm) * Kd + k0 + kk];
            As[kk + 0][mm] = v.x; As[kk + 1][mm] = v.y;
            As[kk + 2][mm] = v.z; As[kk + 3][mm] = v.w;
        }
        {
            int kk = tid >> 4;
            int nn = (tid & 15) * 4;
            *(float4*)&Xs[kk][nn] =
                *(const float4*)&Xb[(size_t)(k0 + kk) * NN + n0 + nn];
        }
        __syncthreads();
#pragma unroll
        for (int kk = 0; kk < 16; kk++) {
            float4 a = *(const float4*)&As[kk][tm];
            float4 x = *(const float4*)&Xs[kk][tn];
            float av[4] = {a.x, a.y, a.z, a.w};
            float xv[4] = {x.x, x.y, x.z, x.w};
#pragma unroll
            for (int i = 0; i < 4; i++)
#pragma unroll
                for (int j = 0; j < 4; j++)
                    acc[i][j] += av[i] * xv[j];
        }
        __syncthreads();
    }
#pragma unroll
    for (int i = 0; i < 4; i++) {
        float4 v = make_float4(acc[i][0], acc[i][1], acc[i][2], acc[i][3]);
        *(float4*)&Ob[(size_t)(m0 + tm + i) * NN + n0 + tn] = v;
    }
}

// ---------------- EdgeConv epilogue v2: V row staged in SMEM, LDS gathers ----------------
// One block per (channel o, batch b). 256 threads.
__global__ void edge_epilogue(const float* __restrict__ UV, const int* __restrict__ idt,
                              float* __restrict__ xcat, int Ch, int rowsPerBatch, int outRow0) {
    int o = blockIdx.x, b = blockIdx.y, tid = threadIdx.x;
    const float* U = UV + ((size_t)b * rowsPerBatch + o) * NPTS;
    const float* V = UV + ((size_t)b * rowsPerBatch + Ch + o) * NPTS;
    const int* it = idt + (size_t)b * KNN * NPTS;
    float* op = xcat + ((size_t)b * 512 + outRow0 + o) * NPTS;

    __shared__ float  sV[NPTS];          // 16 KB: whole V row
    __shared__ float  smax[NPTS];        // 16 KB
    __shared__ double sred[256], s2red[256];
    __shared__ float  smu, srstd;

    // stage V row into smem (float4-coalesced)
#pragma unroll
    for (int i = 0; i < NPTS / 4 / 256; i++)
        ((float4*)sV)[tid + i * 256] = ((const float4*)V)[tid + i * 256];
    __syncthreads();

    double s = 0.0, s2 = 0.0;
#pragma unroll
    for (int itn = 0; itn < NPTS / 256; itn++) {
        int n = tid + itn * 256;
        float u = U[n];
        float m = -3.4e38f, ps = 0.f, pq = 0.f;
#pragma unroll
        for (int kk = 0; kk < KNN; kk++) {
            int j = it[kk * NPTS + n];           // coalesced
            float y = u + sV[j];                 // LDS gather (random bank, ~3-4 way)
            m = fmaxf(m, y);
            ps += y;
            pq += y * y;
        }
        smax[n] = m;
        s += (double)ps; s2 += (double)pq;
    }
    sred[tid] = s; s2red[tid] = s2;
    __syncthreads();
    for (int st = 128; st > 0; st >>= 1) {
        if (tid < st) { sred[tid] += sred[tid + st]; s2red[tid] += s2red[tid + st]; }
        __syncthreads();
    }
    if (tid == 0) {
        double cnt = (double)NPTS * KNN;
        double mu  = sred[0] / cnt;
        double var = s2red[0] / cnt - mu * mu;
        smu   = (float)mu;
        srstd = (float)(1.0 / sqrt(var + 1e-5));
    }
    __syncthreads();
    float mu = smu, r = srstd;
#pragma unroll
    for (int itn = 0; itn < NPTS / 256; itn++) {
        int n = tid + itn * 256;
        float v = (smax[n] - mu) * r;
        op[n] = v >= 0.f ? v : 0.2f * v;
    }
}

// ---------------- final instance-norm (over N) + lrelu (R1 verbatim) ----------------
__global__ void norm_epilogue(const float* __restrict__ Y, float* __restrict__ out) {
    int o = blockIdx.x, b = blockIdx.y, tid = threadIdx.x;
    const float* y = Y + ((size_t)b * CCH + o) * NPTS;
    float* op = out + ((size_t)b * CCH + o) * NPTS;

    __shared__ double sred[256], s2red[256];
    __shared__ float  smu, srstd;

    double s = 0.0, s2 = 0.0;
    for (int n = tid; n < NPTS; n += 256) {
        float v = y[n];
        s += (double)v; s2 += (double)v * (double)v;
    }
    sred[tid] = s; s2red[tid] = s2;
    __syncthreads();
    for (int st = 128; st > 0; st >>= 1) {
        if (tid < st) { sred[tid] += sred[tid + st]; s2red[tid] += s2red[tid + st]; }
        __syncthreads();
    }
    if (tid == 0) {
        double cnt = (double)NPTS;
        double mu  = sred[0] / cnt;
        double var = s2red[0] / cnt - mu * mu;
        smu   = (float)mu;
        srstd = (float)(1.0 / sqrt(var + 1e-5));
    }
    __syncthreads();
    float mu = smu, r = srstd;
    for (int n = tid; n < NPTS; n += 256) {
        float v = (y[n] - mu) * r;
        op[n] = v >= 0.f ? v : 0.2f * v;
    }
}

// ---------------- launch ----------------
extern "C" void kernel_launch(void* const* d_in, const int* in_sizes, int n_in,
                              void* d_out, int out_size) {
    const float* coords = (const float*)d_in[0];
    const float* feats  = (const float*)d_in[1];
    const float* W1     = (const float*)d_in[2];
    const float* W2     = (const float*)d_in[3];
    const float* W3     = (const float*)d_in[4];
    float* out = (float*)d_out;

    float *Wc1, *Wc2, *UV1, *UV2, *xcat, *y3, *kpd;
    int *idt, *kpi;
    cudaGetSymbolAddress((void**)&Wc1,  g_Wc1);
    cudaGetSymbolAddress((void**)&Wc2,  g_Wc2);
    cudaGetSymbolAddress((void**)&UV1,  g_UV1);
    cudaGetSymbolAddress((void**)&UV2,  g_UV2);
    cudaGetSymbolAddress((void**)&xcat, g_xcat);
    cudaGetSymbolAddress((void**)&y3,   g_y3);
    cudaGetSymbolAddress((void**)&idt,  g_idt);
    cudaGetSymbolAddress((void**)&kpd,  g_kpd);
    cudaGetSymbolAddress((void**)&kpi,  g_kpi);

    prep_w<<<256, 256>>>(W1, W2, Wc1, Wc2);
    copy_x0<<<(BATCH * CCH * NPTS / 4 + 255) / 256, 256>>>((const float4*)feats, (float4*)xcat);
    knn_part<<<dim3(NPTS / 256, 4, BATCH), 256>>>(coords, kpd, kpi);
    knn_merge<<<RTOT / 256, 256>>>(kpd, kpi, idt);

    // stage 1: UV1 = Wc1 @ x0
    gemm_kernel<<<dim3(NPTS / 64, 256 / 64, BATCH), 256>>>(
        Wc1, xcat, UV1, 128, (size_t)512 * NPTS, (size_t)256 * NPTS);
    edge_epilogue<<<dim3(128, BATCH), 256>>>(UV1, idt, xcat, 128, 256, 128);

    // stage 2: UV2 = Wc2 @ x1
    gemm_kernel<<<dim3(NPTS / 64, 512 / 64, BATCH), 256>>>(
        Wc2, xcat + (size_t)128 * NPTS, UV2, 128, (size_t)512 * NPTS, (size_t)512 * NPTS);
    edge_epilogue<<<dim3(256, BATCH), 256>>>(UV2, idt, xcat, 256, 512, 256);

    // stage 3: y3 = W3 @ [x0;x1;x2]
    gemm_kernel<<<dim3(NPTS / 64, 128 / 64, BATCH), 256>>>(
        W3, xcat, y3, 512, (size_t)512 * NPTS, (size_t)128 * NPTS);
    norm_epilogue<<<dim3(128, BATCH), 256>>>(y3, out);
}

// round 5
// speedup vs baseline: 1.6105x; 1.5333x over previous
#include <cuda_runtime.h>
#include <math.h>

#define NPTS 4096
#define BATCH 4
#define CCH 128
#define KNN 10
#define RTOT (BATCH * NPTS)

// ---------------- scratch (device globals) ----------------
__device__ float g_Wc1[256 * 128];
__device__ float g_Wc2[512 * 128];
__device__ float g_UV1[BATCH * 256 * NPTS];
__device__ float g_UV2[BATCH * 512 * NPTS];
__device__ float g_xcat[BATCH * 512 * NPTS];
__device__ float g_y3[BATCH * CCH * NPTS];
__device__ int   g_idt[BATCH * KNN * NPTS];   // transposed: [b][k][n]

// ---------------- fused prep: weight combine + x0 copy ----------------
__global__ void prep_all(const float* __restrict__ W1, const float* __restrict__ W2,
                         const float4* __restrict__ f,
                         float* __restrict__ Wc1, float* __restrict__ Wc2,
                         float4* __restrict__ xcat) {
    int i = blockIdx.x * blockDim.x + threadIdx.x;
    const int per = CCH * NPTS / 4;                 // 131072 float4 per batch
    if (i < BATCH * per) {
        int b = i / per, r = i % per;
        xcat[(size_t)b * (512 * NPTS / 4) + r] = f[i];
    }
    if (i < 256 * 128) {
        int o = i / 128, c = i % 128;
        if (o < 128) Wc1[i] = W1[o * 256 + c] - W1[o * 256 + 128 + c];
        else         Wc1[i] = W1[(o - 128) * 256 + 128 + c];
    }
    if (i < 512 * 128) {
        int o = i / 128, c = i % 128;
        if (o < 256) Wc2[i] = W2[o * 256 + c] - W2[o * 256 + 128 + c];
        else         Wc2[i] = W2[(o - 256) * 256 + 128 + c];
    }
}

// ---------------- KNN (monolithic, R1): top-10 nearest, transposed output ----------------
__global__ void knn_kernel(const float* __restrict__ coords, int* __restrict__ idt) {
    int b = blockIdx.y;
    int n = blockIdx.x * blockDim.x + threadIdx.x;
    const float* cb = coords + (size_t)b * 3 * NPTS;
    __shared__ float sx[1024], sy[1024], sz[1024], ss[1024];

    float qx = cb[n], qy = cb[NPTS + n], qz = cb[2 * NPTS + n];
    float qs = qx * qx + qy * qy + qz * qz;

    float dist[KNN];
    int   ind[KNN];
#pragma unroll
    for (int i = 0; i < KNN; i++) { dist[i] = 3.4e38f; ind[i] = 0; }
    float worst = 3.4e38f;

    for (int t = 0; t < NPTS; t += 1024) {
        __syncthreads();
        for (int j = threadIdx.x; j < 1024; j += blockDim.x) {
            float x = cb[t + j], y = cb[NPTS + t + j], z = cb[2 * NPTS + t + j];
            sx[j] = x; sy[j] = y; sz[j] = z; ss[j] = x * x + y * y + z * z;
        }
        __syncthreads();
        for (int j = 0; j < 1024; j++) {
            int jj = t + j;
            float d = qs + ss[j] - 2.f * (qx * sx[j] + qy * sy[j] + qz * sz[j]);
            d = fmaxf(d, 1e-12f);
            if (d < worst && jj != n) {
                int p = KNN - 1;
                while (p > 0 && dist[p - 1] > d) {
                    dist[p] = dist[p - 1]; ind[p] = ind[p - 1]; p--;
                }
                dist[p] = d; ind[p] = jj;
                worst = dist[KNN - 1];
            }
        }
    }
#pragma unroll
    for (int i = 0; i < KNN; i++)
        idt[((size_t)b * KNN + i) * NPTS + n] = ind[i];   // coalesced per k
}

// ---------------- fp32 tiled GEMM (R1 verbatim): O[b] = A (MxK) * X[b] (K x N) ----------
__global__ void gemm_kernel(const float* __restrict__ A, const float* __restrict__ X,
                            float* __restrict__ O, int Kd,
                            size_t strideX, size_t strideO) {
    const int NN = NPTS;
    int b = blockIdx.z;
    const float* Xb = X + (size_t)b * strideX;
    float* Ob = O + (size_t)b * strideO;
    int n0 = blockIdx.x * 64, m0 = blockIdx.y * 64;

    __shared__ float As[16][68];
    __shared__ float Xs[16][64];

    int tid = threadIdx.x;
    int tn = (tid & 15) * 4;
    int tm = (tid >> 4) * 4;
    float acc[4][4] = {};

    for (int k0 = 0; k0 < Kd; k0 += 16) {
        {
            int mm = tid >> 2;
            int kk = (tid & 3) * 4;
            float4 v = *(const float4*)&A[(size_t)(m0 + mm) * Kd + k0 + kk];
            As[kk + 0][mm] = v.x; As[kk + 1][mm] = v.y;
            As[kk + 2][mm] = v.z; As[kk + 3][mm] = v.w;
        }
        {
            int kk = tid >> 4;
            int nn = (tid & 15) * 4;
            *(float4*)&Xs[kk][nn] =
                *(const float4*)&Xb[(size_t)(k0 + kk) * NN + n0 + nn];
        }
        __syncthreads();
#pragma unroll
        for (int kk = 0; kk < 16; kk++) {
            float4 a = *(const float4*)&As[kk][tm];
            float4 x = *(const float4*)&Xs[kk][tn];
            float av[4] = {a.x, a.y, a.z, a.w};
            float xv[4] = {x.x, x.y, x.z, x.w};
#pragma unroll
            for (int i = 0; i < 4; i++)
#pragma unroll
                for (int j = 0; j < 4; j++)
                    acc[i][j] += av[i] * xv[j];
        }
        __syncthreads();
    }
#pragma unroll
    for (int i = 0; i < 4; i++) {
        float4 v = make_float4(acc[i][0], acc[i][1], acc[i][2], acc[i][3]);
        *(float4*)&Ob[(size_t)(m0 + tm + i) * NN + n0 + tn] = v;
    }
}

// ---------------- EdgeConv epilogue v2b: SMEM-staged V row, bounded unroll ----------------
// One block per (channel o, batch b). 256 threads.
__global__ void edge_epilogue(const float* __restrict__ UV, const int* __restrict__ idt,
                              float* __restrict__ xcat, int Ch, int rowsPerBatch, int outRow0) {
    int o = blockIdx.x, b = blockIdx.y, tid = threadIdx.x;
    const float* U = UV + ((size_t)b * rowsPerBatch + o) * NPTS;
    const float* V = UV + ((size_t)b * rowsPerBatch + Ch + o) * NPTS;
    const int* it = idt + (size_t)b * KNN * NPTS;
    float* op = xcat + ((size_t)b * 512 + outRow0 + o) * NPTS;

    __shared__ float  sV[NPTS];
    __shared__ float  smax[NPTS];
    __shared__ double sred[256], s2red[256];
    __shared__ float  smu, srstd;

    // stage V row into smem (float4-coalesced)
    {
        const float4* V4 = (const float4*)V;
        float4* sV4 = (float4*)sV;
        sV4[tid] = V4[tid];
        sV4[tid + 256] = V4[tid + 256];
        sV4[tid + 512] = V4[tid + 512];
        sV4[tid + 768] = V4[tid + 768];
    }
    __syncthreads();

    double s = 0.0, s2 = 0.0;
    for (int n = tid; n < NPTS; n += 256) {     // NOT unrolled (register pressure)
        float u = U[n];
        float m = -3.4e38f, ps = 0.f, pq = 0.f;
#pragma unroll
        for (int kk = 0; kk < KNN; kk++) {
            int j = it[kk * NPTS + n];          // coalesced
            float y = u + sV[j];                // LDS gather
            m = fmaxf(m, y);
            ps += y;
            pq += y * y;
        }
        smax[n] = m;
        s += (double)ps; s2 += (double)pq;
    }
    sred[tid] = s; s2red[tid] = s2;
    __syncthreads();
    for (int st = 128; st > 0; st >>= 1) {
        if (tid < st) { sred[tid] += sred[tid + st]; s2red[tid] += s2red[tid + st]; }
        __syncthreads();
    }
    if (tid == 0) {
        double cnt = (double)NPTS * KNN;
        double mu  = sred[0] / cnt;
        double var = s2red[0] / cnt - mu * mu;
        smu   = (float)mu;
        srstd = (float)(1.0 / sqrt(var + 1e-5));
    }
    __syncthreads();
    float mu = smu, r = srstd;
    for (int n = tid; n < NPTS; n += 256) {
        float v = (smax[n] - mu) * r;
        op[n] = v >= 0.f ? v : 0.2f * v;
    }
}

// ---------------- final instance-norm (over N) + lrelu ----------------
__global__ void norm_epilogue(const float* __restrict__ Y, float* __restrict__ out) {
    int o = blockIdx.x, b = blockIdx.y, tid = threadIdx.x;
    const float* y = Y + ((size_t)b * CCH + o) * NPTS;
    float* op = out + ((size_t)b * CCH + o) * NPTS;

    __shared__ double sred[256], s2red[256];
    __shared__ float  smu, srstd;

    double s = 0.0, s2 = 0.0;
    for (int n = tid; n < NPTS; n += 256) {
        float v = y[n];
        s += (double)v; s2 += (double)v * (double)v;
    }
    sred[tid] = s; s2red[tid] = s2;
    __syncthreads();
    for (int st = 128; st > 0; st >>= 1) {
        if (tid < st) { sred[tid] += sred[tid + st]; s2red[tid] += s2red[tid + st]; }
        __syncthreads();
    }
    if (tid == 0) {
        double cnt = (double)NPTS;
        double mu  = sred[0] / cnt;
        double var = s2red[0] / cnt - mu * mu;
        smu   = (float)mu;
        srstd = (float)(1.0 / sqrt(var + 1e-5));
    }
    __syncthreads();
    float mu = smu, r = srstd;
    for (int n = tid; n < NPTS; n += 256) {
        float v = (y[n] - mu) * r;
        op[n] = v >= 0.f ? v : 0.2f * v;
    }
}

// ---------------- launch ----------------
extern "C" void kernel_launch(void* const* d_in, const int* in_sizes, int n_in,
                              void* d_out, int out_size) {
    const float* coords = (const float*)d_in[0];
    const float* feats  = (const float*)d_in[1];
    const float* W1     = (const float*)d_in[2];
    const float* W2     = (const float*)d_in[3];
    const float* W3     = (const float*)d_in[4];
    float* out = (float*)d_out;

    float *Wc1, *Wc2, *UV1, *UV2, *xcat, *y3;
    int *idt;
    cudaGetSymbolAddress((void**)&Wc1,  g_Wc1);
    cudaGetSymbolAddress((void**)&Wc2,  g_Wc2);
    cudaGetSymbolAddress((void**)&UV1,  g_UV1);
    cudaGetSymbolAddress((void**)&UV2,  g_UV2);
    cudaGetSymbolAddress((void**)&xcat, g_xcat);
    cudaGetSymbolAddress((void**)&y3,   g_y3);
    cudaGetSymbolAddress((void**)&idt,  g_idt);

    // L1: fused prep (weights + x0 copy)
    prep_all<<<(BATCH * CCH * NPTS / 4 + 255) / 256, 256>>>(
        W1, W2, (const float4*)feats, Wc1, Wc2, (float4*)xcat);
    // L2: KNN (independent of gemm1's inputs beyond xcat x0 rows — prep_all done)
    knn_kernel<<<dim3(NPTS / 256, BATCH), 256>>>(coords, idt);
    // L3: gemm1
    gemm_kernel<<<dim3(NPTS / 64, 256 / 64, BATCH), 256>>>(
        Wc1, xcat, UV1, 128, (size_t)512 * NPTS, (size_t)256 * NPTS);
    // L4 (PROFILED SLOT): edge epilogue stage 1
    edge_epilogue<<<dim3(128, BATCH), 256>>>(UV1, idt, xcat, 128, 256, 128);
    // L5: gemm2
    gemm_kernel<<<dim3(NPTS / 64, 512 / 64, BATCH), 256>>>(
        Wc2, xcat + (size_t)128 * NPTS, UV2, 128, (size_t)512 * NPTS, (size_t)512 * NPTS);
    // L6: edge epilogue stage 2
    edge_epilogue<<<dim3(256, BATCH), 256>>>(UV2, idt, xcat, 256, 512, 256);
    // L7: gemm3
    gemm_kernel<<<dim3(NPTS / 64, 128 / 64, BATCH), 256>>>(
        W3, xcat, y3, 512, (size_t)512 * NPTS, (size_t)128 * NPTS);
    // L8: final norm
    norm_epilogue<<<dim3(128, BATCH), 256>>>(y3, out);
}

// round 6
// speedup vs baseline: 2.5719x; 1.5969x over previous
#include <cuda_runtime.h>
#include <math.h>

#define NPTS 4096
#define BATCH 4
#define CCH 128
#define KNN 10
#define RTOT (BATCH * NPTS)

// ---------------- scratch (device globals) ----------------
__device__ float g_Wc1[256 * 128];
__device__ float g_Wc2[512 * 128];
__device__ float g_UV1[BATCH * 256 * NPTS];
__device__ float g_UV2[BATCH * 512 * NPTS];
__device__ float g_xcat[BATCH * 512 * NPTS];
__device__ float g_y3[BATCH * CCH * NPTS];
__device__ int   g_idt[BATCH * KNN * NPTS];        // transposed: [b][k][n]
__device__ float g_kpd[BATCH * 4 * NPTS * KNN];
__device__ int   g_kpi[BATCH * 4 * NPTS * KNN];

// ---------------- weight prep ----------------
__global__ void prep_w(const float* __restrict__ W1, const float* __restrict__ W2,
                       float* __restrict__ Wc1, float* __restrict__ Wc2) {
    int i = blockIdx.x * blockDim.x + threadIdx.x;
    if (i < 256 * 128) {
        int o = i / 128, c = i % 128;
        if (o < 128) Wc1[i] = W1[o * 256 + c] - W1[o * 256 + 128 + c];
        else         Wc1[i] = W1[(o - 128) * 256 + 128 + c];
    }
    if (i < 512 * 128) {
        int o = i / 128, c = i % 128;
        if (o < 256) Wc2[i] = W2[o * 256 + c] - W2[o * 256 + 128 + c];
        else         Wc2[i] = W2[(o - 256) * 256 + 128 + c];
    }
}

// ---------------- copy x0 into xcat rows [0,128) ----------------
__global__ void copy_x0(const float4* __restrict__ f, float4* __restrict__ xcat) {
    int i = blockIdx.x * blockDim.x + threadIdx.x;
    const int per = CCH * NPTS / 4;
    if (i >= BATCH * per) return;
    int b = i / per, r = i % per;
    xcat[(size_t)b * (512 * NPTS / 4) + r] = f[i];
}

// ---------------- KNN pass1: per-1024-slice top-10, REGISTER-ONLY lists ----------------
__global__ void knn_part(const float* __restrict__ coords,
                         float* __restrict__ pd, int* __restrict__ pi) {
    int b = blockIdx.z, s = blockIdx.y;
    int n = blockIdx.x * 256 + threadIdx.x;
    const float* cb = coords + (size_t)b * 3 * NPTS;
    __shared__ float sx[1024], sy[1024], sz[1024], ss[1024];
    int base = s * 1024;
    for (int j = threadIdx.x; j < 1024; j += 256) {
        float x = cb[base + j], y = cb[NPTS + base + j], z = cb[2 * NPTS + base + j];
        sx[j] = x; sy[j] = y; sz[j] = z; ss[j] = x * x + y * y + z * z;
    }
    __syncthreads();
    float qx = cb[n], qy = cb[NPTS + n], qz = cb[2 * NPTS + n];
    float qs = qx * qx + qy * qy + qz * qz;

    float dist[KNN]; int ind[KNN];
#pragma unroll
    for (int i = 0; i < KNN; i++) { dist[i] = 3.4e38f; ind[i] = 0x7fffffff; }

    for (int j = 0; j < 1024; j++) {
        int jj = base + j;
        float d = qs + ss[j] - 2.f * (qx * sx[j] + qy * sy[j] + qz * sz[j]);
        d = fmaxf(d, 1e-12f);
        if (d < dist[KNN - 1] && jj != n) {
            // sorted bubble-insert, all indices compile-time constant (registers only)
            dist[KNN - 1] = d; ind[KNN - 1] = jj;
#pragma unroll
            for (int i = KNN - 1; i > 0; i--) {
                bool sw = dist[i] < dist[i - 1];   // strict: stable for ties
                float td = sw ? dist[i - 1] : dist[i];
                int   ti = sw ? ind[i - 1]  : ind[i];
                dist[i - 1] = sw ? dist[i] : dist[i - 1];
                ind[i - 1]  = sw ? ind[i]  : ind[i - 1];
                dist[i] = td; ind[i] = ti;
            }
        }
    }
    size_t off = ((size_t)(b * 4 + s) * NPTS + n) * KNN;
#pragma unroll
    for (int i = 0; i < KNN; i++) { pd[off + i] = dist[i]; pi[off + i] = ind[i]; }
}

// ---------------- KNN merge: 4 sorted lists -> final 10, transposed output ----------------
__global__ void knn_merge(const float* __restrict__ pd, const int* __restrict__ pi,
                          int* __restrict__ idt) {
    int t = blockIdx.x * 256 + threadIdx.x;
    if (t >= RTOT) return;
    int b = t >> 12, n = t & (NPTS - 1);
    const float* pdp[4]; const int* pip[4]; int pos[4] = {0, 0, 0, 0};
#pragma unroll
    for (int s = 0; s < 4; s++) {
        size_t off = ((size_t)(b * 4 + s) * NPTS + n) * KNN;
        pdp[s] = pd + off; pip[s] = pi + off;
    }
#pragma unroll
    for (int r = 0; r < KNN; r++) {
        float best = 3.5e38f; int bs = 0, bidx = 0x7fffffff;
#pragma unroll
        for (int s = 0; s < 4; s++) {
            float dv = pdp[s][pos[s]];
            int iv = pip[s][pos[s]];
            if (dv < best || (dv == best && iv < bidx)) { best = dv; bs = s; bidx = iv; }
        }
        idt[((size_t)b * KNN + r) * NPTS + n] = bidx;
        pos[bs]++;
    }
}

// ---------------- fp32 tiled GEMM (R1 verbatim): O[b] = A (MxK) * X[b] (K x N) ----------
__global__ void gemm_kernel(const float* __restrict__ A, const float* __restrict__ X,
                            float* __restrict__ O, int Kd,
                            size_t strideX, size_t strideO) {
    const int NN = NPTS;
    int b = blockIdx.z;
    const float* Xb = X + (size_t)b * strideX;
    float* Ob = O + (size_t)b * strideO;
    int n0 = blockIdx.x * 64, m0 = blockIdx.y * 64;

    __shared__ float As[16][68];
    __shared__ float Xs[16][64];

    int tid = threadIdx.x;
    int tn = (tid & 15) * 4;
    int tm = (tid >> 4) * 4;
    float acc[4][4] = {};

    for (int k0 = 0; k0 < Kd; k0 += 16) {
        {
            int mm = tid >> 2;
            int kk = (tid & 3) * 4;
            float4 v = *(const float4*)&A[(size_t)(m0 + mm) * Kd + k0 + kk];
            As[kk + 0][mm] = v.x; As[kk + 1][mm] = v.y;
            As[kk + 2][mm] = v.z; As[kk + 3][mm] = v.w;
        }
        {
            int kk = tid >> 4;
            int nn = (tid & 15) * 4;
            *(float4*)&Xs[kk][nn] =
                *(const float4*)&Xb[(size_t)(k0 + kk) * NN + n0 + nn];
        }
        __syncthreads();
#pragma unroll
        for (int kk = 0; kk < 16; kk++) {
            float4 a = *(const float4*)&As[kk][tm];
            float4 x = *(const float4*)&Xs[kk][tn];
            float av[4] = {a.x, a.y, a.z, a.w};
            float xv[4] = {x.x, x.y, x.z, x.w};
#pragma unroll
            for (int i = 0; i < 4; i++)
#pragma unroll
                for (int j = 0; j < 4; j++)
                    acc[i][j] += av[i] * xv[j];
        }
        __syncthreads();
    }
#pragma unroll
    for (int i = 0; i < 4; i++) {
        float4 v = make_float4(acc[i][0], acc[i][1], acc[i][2], acc[i][3]);
        *(float4*)&Ob[(size_t)(m0 + tm + i) * NN + n0 + tn] = v;
    }
}

// ---------------- EdgeConv epilogue v2b (R5 verbatim): SMEM-staged V row ----------------
__global__ void edge_epilogue(const float* __restrict__ UV, const int* __restrict__ idt,
                              float* __restrict__ xcat, int Ch, int rowsPerBatch, int outRow0) {
    int o = blockIdx.x, b = blockIdx.y, tid = threadIdx.x;
    const float* U = UV + ((size_t)b * rowsPerBatch + o) * NPTS;
    const float* V = UV + ((size_t)b * rowsPerBatch + Ch + o) * NPTS;
    const int* it = idt + (size_t)b * KNN * NPTS;
    float* op = xcat + ((size_t)b * 512 + outRow0 + o) * NPTS;

    __shared__ float  sV[NPTS];
    __shared__ float  smax[NPTS];
    __shared__ double sred[256], s2red[256];
    __shared__ float  smu, srstd;

    {
        const float4* V4 = (const float4*)V;
        float4* sV4 = (float4*)sV;
        sV4[tid] = V4[tid];
        sV4[tid + 256] = V4[tid + 256];
        sV4[tid + 512] = V4[tid + 512];
        sV4[tid + 768] = V4[tid + 768];
    }
    __syncthreads();

    double s = 0.0, s2 = 0.0;
    for (int n = tid; n < NPTS; n += 256) {
        float u = U[n];
        float m = -3.4e38f, ps = 0.f, pq = 0.f;
#pragma unroll
        for (int kk = 0; kk < KNN; kk++) {
            int j = it[kk * NPTS + n];
            float y = u + sV[j];
            m = fmaxf(m, y);
            ps += y;
            pq += y * y;
        }
        smax[n] = m;
        s += (double)ps; s2 += (double)pq;
    }
    sred[tid] = s; s2red[tid] = s2;
    __syncthreads();
    for (int st = 128; st > 0; st >>= 1) {
        if (tid < st) { sred[tid] += sred[tid + st]; s2red[tid] += s2red[tid + st]; }
        __syncthreads();
    }
    if (tid == 0) {
        double cnt = (double)NPTS * KNN;
        double mu  = sred[0] / cnt;
        double var = s2red[0] / cnt - mu * mu;
        smu   = (float)mu;
        srstd = (float)(1.0 / sqrt(var + 1e-5));
    }
    __syncthreads();
    float mu = smu, r = srstd;
    for (int n = tid; n < NPTS; n += 256) {
        float v = (smax[n] - mu) * r;
        op[n] = v >= 0.f ? v : 0.2f * v;
    }
}

// ---------------- final instance-norm (over N) + lrelu ----------------
__global__ void norm_epilogue(const float* __restrict__ Y, float* __restrict__ out) {
    int o = blockIdx.x, b = blockIdx.y, tid = threadIdx.x;
    const float* y = Y + ((size_t)b * CCH + o) * NPTS;
    float* op = out + ((size_t)b * CCH + o) * NPTS;

    __shared__ double sred[256], s2red[256];
    __shared__ float  smu, srstd;

    double s = 0.0, s2 = 0.0;
    for (int n = tid; n < NPTS; n += 256) {
        float v = y[n];
        s += (double)v; s2 += (double)v * (double)v;
    }
    sred[tid] = s; s2red[tid] = s2;
    __syncthreads();
    for (int st = 128; st > 0; st >>= 1) {
        if (tid < st) { sred[tid] += sred[tid + st]; s2red[tid] += s2red[tid + st]; }
        __syncthreads();
    }
    if (tid == 0) {
        double cnt = (double)NPTS;
        double mu  = sred[0] / cnt;
        double var = s2red[0] / cnt - mu * mu;
        smu   = (float)mu;
        srstd = (float)(1.0 / sqrt(var + 1e-5));
    }
    __syncthreads();
    float mu = smu, r = srstd;
    for (int n = tid; n < NPTS; n += 256) {
        float v = (y[n] - mu) * r;
        op[n] = v >= 0.f ? v : 0.2f * v;
    }
}

// ---------------- launch ----------------
extern "C" void kernel_launch(void* const* d_in, const int* in_sizes, int n_in,
                              void* d_out, int out_size) {
    const float* coords = (const float*)d_in[0];
    const float* feats  = (const float*)d_in[1];
    const float* W1     = (const float*)d_in[2];
    const float* W2     = (const float*)d_in[3];
    const float* W3     = (const float*)d_in[4];
    float* out = (float*)d_out;

    float *Wc1, *Wc2, *UV1, *UV2, *xcat, *y3, *kpd;
    int *idt, *kpi;
    cudaGetSymbolAddress((void**)&Wc1,  g_Wc1);
    cudaGetSymbolAddress((void**)&Wc2,  g_Wc2);
    cudaGetSymbolAddress((void**)&UV1,  g_UV1);
    cudaGetSymbolAddress((void**)&UV2,  g_UV2);
    cudaGetSymbolAddress((void**)&xcat, g_xcat);
    cudaGetSymbolAddress((void**)&y3,   g_y3);
    cudaGetSymbolAddress((void**)&idt,  g_idt);
    cudaGetSymbolAddress((void**)&kpd,  g_kpd);
    cudaGetSymbolAddress((void**)&kpi,  g_kpi);

    // L1, L2: prep (independent)
    prep_w<<<256, 256>>>(W1, W2, Wc1, Wc2);
    copy_x0<<<(BATCH * CCH * NPTS / 4 + 255) / 256, 256>>>((const float4*)feats, (float4*)xcat);
    // L3: gemm1 (needs L1+L2)
    gemm_kernel<<<dim3(NPTS / 64, 256 / 64, BATCH), 256>>>(
        Wc1, xcat, UV1, 128, (size_t)512 * NPTS, (size_t)256 * NPTS);
    // L4 (PROFILED SLOT): knn_part
    knn_part<<<dim3(NPTS / 256, 4, BATCH), 256>>>(coords, kpd, kpi);
    // L5: knn_merge
    knn_merge<<<RTOT / 256, 256>>>(kpd, kpi, idt);
    // L6: edge epilogue stage 1
    edge_epilogue<<<dim3(128, BATCH), 256>>>(UV1, idt, xcat, 128, 256, 128);
    // L7: gemm2
    gemm_kernel<<<dim3(NPTS / 64, 512 / 64, BATCH), 256>>>(
        Wc2, xcat + (size_t)128 * NPTS, UV2, 128, (size_t)512 * NPTS, (size_t)512 * NPTS);
    // L8: edge epilogue stage 2
    edge_epilogue<<<dim3(256, BATCH), 256>>>(UV2, idt, xcat, 256, 512, 256);
    // L9: gemm3
    gemm_kernel<<<dim3(NPTS / 64, 128 / 64, BATCH), 256>>>(
        W3, xcat, y3, 512, (size_t)512 * NPTS, (size_t)128 * NPTS);
    // L10: final norm
    norm_epilogue<<<dim3(128, BATCH), 256>>>(y3, out);
}

// round 7
// speedup vs baseline: 2.7255x; 1.0597x over previous
#include <cuda_runtime.h>
#include <math.h>

#define NPTS 4096
#define BATCH 4
#define CCH 128
#define KNN 10
#define RTOT (BATCH * NPTS)

// ---------------- scratch (device globals) ----------------
__device__ float g_Wc1[256 * 128];
__device__ float g_Wc2[512 * 128];
__device__ float g_UV1[BATCH * 256 * NPTS];
__device__ float g_UV2[BATCH * 512 * NPTS];
__device__ float g_xcat[BATCH * 512 * NPTS];
__device__ float g_y3[BATCH * CCH * NPTS];
__device__ int   g_idt[BATCH * KNN * NPTS];        // transposed: [b][k][n]
__device__ float g_kpd[BATCH * 4 * NPTS * KNN];
__device__ int   g_kpi[BATCH * 4 * NPTS * KNN];

// ---------------- weight prep ----------------
__global__ void prep_w(const float* __restrict__ W1, const float* __restrict__ W2,
                       float* __restrict__ Wc1, float* __restrict__ Wc2) {
    int i = blockIdx.x * blockDim.x + threadIdx.x;
    if (i < 256 * 128) {
        int o = i / 128, c = i % 128;
        if (o < 128) Wc1[i] = W1[o * 256 + c] - W1[o * 256 + 128 + c];
        else         Wc1[i] = W1[(o - 128) * 256 + 128 + c];
    }
    if (i < 512 * 128) {
        int o = i / 128, c = i % 128;
        if (o < 256) Wc2[i] = W2[o * 256 + c] - W2[o * 256 + 128 + c];
        else         Wc2[i] = W2[(o - 256) * 256 + 128 + c];
    }
}

// ---------------- copy x0 into xcat rows [0,128) ----------------
__global__ void copy_x0(const float4* __restrict__ f, float4* __restrict__ xcat) {
    int i = blockIdx.x * blockDim.x + threadIdx.x;
    const int per = CCH * NPTS / 4;
    if (i >= BATCH * per) return;
    int b = i / per, r = i % per;
    xcat[(size_t)b * (512 * NPTS / 4) + r] = f[i];
}

// ---------------- KNN pass1: per-1024-slice top-10, packed float4 candidates --------
__global__ void knn_part(const float* __restrict__ coords,
                         float* __restrict__ pd, int* __restrict__ pi) {
    int b = blockIdx.z, s = blockIdx.y;
    int n = blockIdx.x * 256 + threadIdx.x;
    const float* cb = coords + (size_t)b * 3 * NPTS;
    __shared__ float4 sc[1024];
    int base = s * 1024;
    for (int j = threadIdx.x; j < 1024; j += 256) {
        float x = cb[base + j], y = cb[NPTS + base + j], z = cb[2 * NPTS + base + j];
        sc[j] = make_float4(x, y, z, x * x + y * y + z * z);
    }
    __syncthreads();
    float qx = cb[n], qy = cb[NPTS + n], qz = cb[2 * NPTS + n];
    float qs = qx * qx + qy * qy + qz * qz;

    float dist[KNN]; int ind[KNN];
#pragma unroll
    for (int i = 0; i < KNN; i++) { dist[i] = 3.4e38f; ind[i] = 0x7fffffff; }

#pragma unroll 4
    for (int j = 0; j < 1024; j++) {
        int jj = base + j;
        float4 c = sc[j];                       // LDS.128 broadcast
        float dot = qx * c.x + qy * c.y + qz * c.z;
        float d = fmaf(-2.f, dot, qs + c.w);
        d = fmaxf(d, 1e-12f);
        if (d < dist[KNN - 1] && jj != n) {
            dist[KNN - 1] = d; ind[KNN - 1] = jj;
#pragma unroll
            for (int i = KNN - 1; i > 0; i--) {
                bool sw = dist[i] < dist[i - 1];
                float td = sw ? dist[i - 1] : dist[i];
                int   ti = sw ? ind[i - 1]  : ind[i];
                dist[i - 1] = sw ? dist[i] : dist[i - 1];
                ind[i - 1]  = sw ? ind[i]  : ind[i - 1];
                dist[i] = td; ind[i] = ti;
            }
        }
    }
    size_t off = ((size_t)(b * 4 + s) * NPTS + n) * KNN;
#pragma unroll
    for (int i = 0; i < KNN; i++) { pd[off + i] = dist[i]; pi[off + i] = ind[i]; }
}

// ---------------- KNN merge: 4 sorted lists -> final 10, transposed output ----------------
__global__ void knn_merge(const float* __restrict__ pd, const int* __restrict__ pi,
                          int* __restrict__ idt) {
    int t = blockIdx.x * 256 + threadIdx.x;
    if (t >= RTOT) return;
    int b = t >> 12, n = t & (NPTS - 1);
    const float* pdp[4]; const int* pip[4]; int pos[4] = {0, 0, 0, 0};
#pragma unroll
    for (int s = 0; s < 4; s++) {
        size_t off = ((size_t)(b * 4 + s) * NPTS + n) * KNN;
        pdp[s] = pd + off; pip[s] = pi + off;
    }
#pragma unroll
    for (int r = 0; r < KNN; r++) {
        float best = 3.5e38f; int bs = 0, bidx = 0x7fffffff;
#pragma unroll
        for (int s = 0; s < 4; s++) {
            float dv = pdp[s][pos[s]];
            int iv = pip[s][pos[s]];
            if (dv < best || (dv == best && iv < bidx)) { best = dv; bs = s; bidx = iv; }
        }
        idt[((size_t)b * KNN + r) * NPTS + n] = bidx;
        pos[bs]++;
    }
}

// ------------- fp32 GEMM v2: 128x128 tile, 256 thr, 8x8 micro (conflict-free) -------------
// O[b] = A (MxK) * X[b] (K x NPTS). grid (NPTS/128, M/128, BATCH).
__global__ void gemm_kernel(const float* __restrict__ A, const float* __restrict__ X,
                            float* __restrict__ O, int Kd,
                            size_t strideX, size_t strideO) {
    const int NN = NPTS;
    int b = blockIdx.z;
    const float* Xb = X + (size_t)b * strideX;
    float* Ob = O + (size_t)b * strideO;
    int n0 = blockIdx.x * 128, m0 = blockIdx.y * 128;

    __shared__ float As[16][132];
    __shared__ float Xs[16][132];

    int tid = threadIdx.x;
    int tr = tid & 15;          // n quad
    int tm = tid >> 4;          // m quad
    float acc[8][8] = {};

    for (int k0 = 0; k0 < Kd; k0 += 16) {
        // A tile: 128 rows x 16 k, each thread 2 float4 (transposed store)
#pragma unroll
        for (int t = 0; t < 2; t++) {
            int f = tid * 2 + t;
            int rr = f >> 2, kc = (f & 3) * 4;
            float4 v = *(const float4*)&A[(size_t)(m0 + rr) * Kd + k0 + kc];
            As[kc + 0][rr] = v.x; As[kc + 1][rr] = v.y;
            As[kc + 2][rr] = v.z; As[kc + 3][rr] = v.w;
        }
        // X tile: 16 k x 128 n, coalesced float4
#pragma unroll
        for (int t = 0; t < 2; t++) {
            int f = tid * 2 + t;
            int kk = f >> 5, nc = (f & 31) * 4;
            *(float4*)&Xs[kk][nc] =
                *(const float4*)&Xb[(size_t)(k0 + kk) * NN + n0 + nc];
        }
        __syncthreads();
#pragma unroll
        for (int kk = 0; kk < 16; kk++) {
            float xr[8], am[8];
            *(float4*)&xr[0] = *(const float4*)&Xs[kk][tr * 4];
            *(float4*)&xr[4] = *(const float4*)&Xs[kk][tr * 4 + 64];
            *(float4*)&am[0] = *(const float4*)&As[kk][tm * 4];
            *(float4*)&am[4] = *(const float4*)&As[kk][tm * 4 + 64];
#pragma unroll
            for (int i = 0; i < 8; i++)
#pragma unroll
                for (int j = 0; j < 8; j++)
                    acc[i][j] += am[i] * xr[j];
        }
        __syncthreads();
    }
#pragma unroll
    for (int h = 0; h < 2; h++) {
#pragma unroll
        for (int i = 0; i < 4; i++) {
            int m = m0 + tm * 4 + i + h * 64;
            float* orow = Ob + (size_t)m * NN + n0;
            *(float4*)&orow[tr * 4] =
                make_float4(acc[h * 4 + i][0], acc[h * 4 + i][1], acc[h * 4 + i][2], acc[h * 4 + i][3]);
            *(float4*)&orow[tr * 4 + 64] =
                make_float4(acc[h * 4 + i][4], acc[h * 4 + i][5], acc[h * 4 + i][6], acc[h * 4 + i][7]);
        }
    }
}

// ---------------- EdgeConv epilogue v3: SMEM-staged V row, 2-way ILP ----------------
__global__ void edge_epilogue(const float* __restrict__ UV, const int* __restrict__ idt,
                              float* __restrict__ xcat, int Ch, int rowsPerBatch, int outRow0) {
    int o = blockIdx.x, b = blockIdx.y, tid = threadIdx.x;
    const float* U = UV + ((size_t)b * rowsPerBatch + o) * NPTS;
    const float* V = UV + ((size_t)b * rowsPerBatch + Ch + o) * NPTS;
    const int* it = idt + (size_t)b * KNN * NPTS;
    float* op = xcat + ((size_t)b * 512 + outRow0 + o) * NPTS;

    __shared__ float  sV[NPTS];
    __shared__ float  smax[NPTS];
    __shared__ double sred[256], s2red[256];
    __shared__ float  smu, srstd;

    {
        const float4* V4 = (const float4*)V;
        float4* sV4 = (float4*)sV;
        sV4[tid] = V4[tid];
        sV4[tid + 256] = V4[tid + 256];
        sV4[tid + 512] = V4[tid + 512];
        sV4[tid + 768] = V4[tid + 768];
    }
    __syncthreads();

    double s = 0.0, s2 = 0.0;
    for (int n = tid; n < NPTS / 2; n += 256) {
        int n2 = n + NPTS / 2;
        float ua = U[n], ub = U[n2];
        float ma = -3.4e38f, mb = -3.4e38f;
        float psa = 0.f, pqa = 0.f, psb = 0.f, pqb = 0.f;
#pragma unroll
        for (int kk = 0; kk < KNN; kk++) {
            int ja = it[kk * NPTS + n];
            int jb = it[kk * NPTS + n2];
            float ya = ua + sV[ja];
            float yb = ub + sV[jb];
            ma = fmaxf(ma, ya); psa += ya; pqa += ya * ya;
            mb = fmaxf(mb, yb); psb += yb; pqb += yb * yb;
        }
        smax[n] = ma; smax[n2] = mb;
        s += (double)(psa) + (double)(psb);
        s2 += (double)(pqa) + (double)(pqb);
    }
    sred[tid] = s; s2red[tid] = s2;
    __syncthreads();
    for (int st = 128; st > 0; st >>= 1) {
        if (tid < st) { sred[tid] += sred[tid + st]; s2red[tid] += s2red[tid + st]; }
        __syncthreads();
    }
    if (tid == 0) {
        double cnt = (double)NPTS * KNN;
        double mu  = sred[0] / cnt;
        double var = s2red[0] / cnt - mu * mu;
        smu   = (float)mu;
        srstd = (float)(1.0 / sqrt(var + 1e-5));
    }
    __syncthreads();
    float mu = smu, r = srstd;
    for (int n = tid; n < NPTS; n += 256) {
        float v = (smax[n] - mu) * r;
        op[n] = v >= 0.f ? v : 0.2f * v;
    }
}

// ---------------- final instance-norm (over N) + lrelu ----------------
__global__ void norm_epilogue(const float* __restrict__ Y, float* __restrict__ out) {
    int o = blockIdx.x, b = blockIdx.y, tid = threadIdx.x;
    const float* y = Y + ((size_t)b * CCH + o) * NPTS;
    float* op = out + ((size_t)b * CCH + o) * NPTS;

    __shared__ double sred[256], s2red[256];
    __shared__ float  smu, srstd;

    double s = 0.0, s2 = 0.0;
    for (int n = tid; n < NPTS; n += 256) {
        float v = y[n];
        s += (double)v; s2 += (double)v * (double)v;
    }
    sred[tid] = s; s2red[tid] = s2;
    __syncthreads();
    for (int st = 128; st > 0; st >>= 1) {
        if (tid < st) { sred[tid] += sred[tid + st]; s2red[tid] += s2red[tid + st]; }
        __syncthreads();
    }
    if (tid == 0) {
        double cnt = (double)NPTS;
        double mu  = sred[0] / cnt;
        double var = s2red[0] / cnt - mu * mu;
        smu   = (float)mu;
        srstd = (float)(1.0 / sqrt(var + 1e-5));
    }
    __syncthreads();
    float mu = smu, r = srstd;
    for (int n = tid; n < NPTS; n += 256) {
        float v = (y[n] - mu) * r;
        op[n] = v >= 0.f ? v : 0.2f * v;
    }
}

// ---------------- launch ----------------
extern "C" void kernel_launch(void* const* d_in, const int* in_sizes, int n_in,
                              void* d_out, int out_size) {
    const float* coords = (const float*)d_in[0];
    const float* feats  = (const float*)d_in[1];
    const float* W1     = (const float*)d_in[2];
    const float* W2     = (const float*)d_in[3];
    const float* W3     = (const float*)d_in[4];
    float* out = (float*)d_out;

    float *Wc1, *Wc2, *UV1, *UV2, *xcat, *y3, *kpd;
    int *idt, *kpi;
    cudaGetSymbolAddress((void**)&Wc1,  g_Wc1);
    cudaGetSymbolAddress((void**)&Wc2,  g_Wc2);
    cudaGetSymbolAddress((void**)&UV1,  g_UV1);
    cudaGetSymbolAddress((void**)&UV2,  g_UV2);
    cudaGetSymbolAddress((void**)&xcat, g_xcat);
    cudaGetSymbolAddress((void**)&y3,   g_y3);
    cudaGetSymbolAddress((void**)&idt,  g_idt);
    cudaGetSymbolAddress((void**)&kpd,  g_kpd);
    cudaGetSymbolAddress((void**)&kpi,  g_kpi);

    // L1, L2: prep
    prep_w<<<256, 256>>>(W1, W2, Wc1, Wc2);
    copy_x0<<<(BATCH * CCH * NPTS / 4 + 255) / 256, 256>>>((const float4*)feats, (float4*)xcat);
    // L3: knn_part
    knn_part<<<dim3(NPTS / 256, 4, BATCH), 256>>>(coords, kpd, kpi);
    // L4 (PROFILED SLOT): new gemm1
    gemm_kernel<<<dim3(NPTS / 128, 256 / 128, BATCH), 256>>>(
        Wc1, xcat, UV1, 128, (size_t)512 * NPTS, (size_t)256 * NPTS);
    // L5: knn_merge
    knn_merge<<<RTOT / 256, 256>>>(kpd, kpi, idt);
    // L6: edge epilogue stage 1
    edge_epilogue<<<dim3(128, BATCH), 256>>>(UV1, idt, xcat, 128, 256, 128);
    // L7: gemm2
    gemm_kernel<<<dim3(NPTS / 128, 512 / 128, BATCH), 256>>>(
        Wc2, xcat + (size_t)128 * NPTS, UV2, 128, (size_t)512 * NPTS, (size_t)512 * NPTS);
    // L8: edge epilogue stage 2
    edge_epilogue<<<dim3(256, BATCH), 256>>>(UV2, idt, xcat, 256, 512, 256);
    // L9: gemm3
    gemm_kernel<<<dim3(NPTS / 128, 128 / 128, BATCH), 256>>>(
        W3, xcat, y3, 512, (size_t)512 * NPTS, (size_t)128 * NPTS);
    // L10: final norm
    norm_epilogue<<<dim3(128, BATCH), 256>>>(y3, out);
}

// round 8
// speedup vs baseline: 2.8020x; 1.0281x over previous
#include <cuda_runtime.h>
#include <math.h>

#define NPTS 4096
#define BATCH 4
#define CCH 128
#define KNN 10
#define RTOT (BATCH * NPTS)

typedef unsigned long long u64;

// ---------------- scratch (device globals) ----------------
__device__ float g_Wc1[256 * 128];
__device__ float g_Wc2[512 * 128];
__device__ float g_UV1[BATCH * 256 * NPTS];
__device__ float g_UV2[BATCH * 512 * NPTS];
__device__ float g_xcat[BATCH * 512 * NPTS];
__device__ float g_y3[BATCH * CCH * NPTS];
__device__ int   g_idt[BATCH * KNN * NPTS];        // transposed: [b][k][n]
__device__ float g_kpd[BATCH * 4 * NPTS * KNN];
__device__ int   g_kpi[BATCH * 4 * NPTS * KNN];

// ---------------- f32x2 helpers ----------------
__device__ __forceinline__ u64 bcast2(float a) {
    u64 r; asm("mov.b64 %0, {%1, %1};" : "=l"(r) : "f"(a)); return r;
}
__device__ __forceinline__ void fma2(u64& d, u64 a, u64 b) {
    asm("fma.rn.f32x2 %0, %1, %2, %0;" : "+l"(d) : "l"(a), "l"(b));
}

// ---------------- weight prep ----------------
__global__ void prep_w(const float* __restrict__ W1, const float* __restrict__ W2,
                       float* __restrict__ Wc1, float* __restrict__ Wc2) {
    int i = blockIdx.x * blockDim.x + threadIdx.x;
    if (i < 256 * 128) {
        int o = i / 128, c = i % 128;
        if (o < 128) Wc1[i] = W1[o * 256 + c] - W1[o * 256 + 128 + c];
        else         Wc1[i] = W1[(o - 128) * 256 + 128 + c];
    }
    if (i < 512 * 128) {
        int o = i / 128, c = i % 128;
        if (o < 256) Wc2[i] = W2[o * 256 + c] - W2[o * 256 + 128 + c];
        else         Wc2[i] = W2[(o - 256) * 256 + 128 + c];
    }
}

// ---------------- copy x0 into xcat rows [0,128) ----------------
__global__ void copy_x0(const float4* __restrict__ f, float4* __restrict__ xcat) {
    int i = blockIdx.x * blockDim.x + threadIdx.x;
    const int per = CCH * NPTS / 4;
    if (i >= BATCH * per) return;
    int b = i / per, r = i % per;
    xcat[(size_t)b * (512 * NPTS / 4) + r] = f[i];
}

// ---------------- KNN pass1 (R7 verbatim) ----------------
__global__ void knn_part(const float* __restrict__ coords,
                         float* __restrict__ pd, int* __restrict__ pi) {
    int b = blockIdx.z, s = blockIdx.y;
    int n = blockIdx.x * 256 + threadIdx.x;
    const float* cb = coords + (size_t)b * 3 * NPTS;
    __shared__ float4 sc[1024];
    int base = s * 1024;
    for (int j = threadIdx.x; j < 1024; j += 256) {
        float x = cb[base + j], y = cb[NPTS + base + j], z = cb[2 * NPTS + base + j];
        sc[j] = make_float4(x, y, z, x * x + y * y + z * z);
    }
    __syncthreads();
    float qx = cb[n], qy = cb[NPTS + n], qz = cb[2 * NPTS + n];
    float qs = qx * qx + qy * qy + qz * qz;

    float dist[KNN]; int ind[KNN];
#pragma unroll
    for (int i = 0; i < KNN; i++) { dist[i] = 3.4e38f; ind[i] = 0x7fffffff; }

#pragma unroll 4
    for (int j = 0; j < 1024; j++) {
        int jj = base + j;
        float4 c = sc[j];
        float dot = qx * c.x + qy * c.y + qz * c.z;
        float d = fmaf(-2.f, dot, qs + c.w);
        d = fmaxf(d, 1e-12f);
        if (d < dist[KNN - 1] && jj != n) {
            dist[KNN - 1] = d; ind[KNN - 1] = jj;
#pragma unroll
            for (int i = KNN - 1; i > 0; i--) {
                bool sw = dist[i] < dist[i - 1];
                float td = sw ? dist[i - 1] : dist[i];
                int   ti = sw ? ind[i - 1]  : ind[i];
                dist[i - 1] = sw ? dist[i] : dist[i - 1];
                ind[i - 1]  = sw ? ind[i]  : ind[i - 1];
                dist[i] = td; ind[i] = ti;
            }
        }
    }
    size_t off = ((size_t)(b * 4 + s) * NPTS + n) * KNN;
#pragma unroll
    for (int i = 0; i < KNN; i++) { pd[off + i] = dist[i]; pi[off + i] = ind[i]; }
}

// ---------------- KNN merge (R7 verbatim) ----------------
__global__ void knn_merge(const float* __restrict__ pd, const int* __restrict__ pi,
                          int* __restrict__ idt) {
    int t = blockIdx.x * 256 + threadIdx.x;
    if (t >= RTOT) return;
    int b = t >> 12, n = t & (NPTS - 1);
    const float* pdp[4]; const int* pip[4]; int pos[4] = {0, 0, 0, 0};
#pragma unroll
    for (int s = 0; s < 4; s++) {
        size_t off = ((size_t)(b * 4 + s) * NPTS + n) * KNN;
        pdp[s] = pd + off; pip[s] = pi + off;
    }
#pragma unroll
    for (int r = 0; r < KNN; r++) {
        float best = 3.5e38f; int bs = 0, bidx = 0x7fffffff;
#pragma unroll
        for (int s = 0; s < 4; s++) {
            float dv = pdp[s][pos[s]];
            int iv = pip[s][pos[s]];
            if (dv < best || (dv == best && iv < bidx)) { best = dv; bs = s; bidx = iv; }
        }
        idt[((size_t)b * KNN + r) * NPTS + n] = bidx;
        pos[bs]++;
    }
}

// ------------- fp32 GEMM v3: 128x128 tile, 8x8 micro, f32x2 packed FMA -------------
// O[b] = A (MxK) * X[b] (K x NPTS). grid (NPTS/128, M/128, BATCH).
__global__ void gemm_kernel(const float* __restrict__ A, const float* __restrict__ X,
                            float* __restrict__ O, int Kd,
                            size_t strideX, size_t strideO) {
    const int NN = NPTS;
    int b = blockIdx.z;
    const float* Xb = X + (size_t)b * strideX;
    float* Ob = O + (size_t)b * strideO;
    int n0 = blockIdx.x * 128, m0 = blockIdx.y * 128;

    __shared__ float As[16][132];
    __shared__ float Xs[16][132];

    int tid = threadIdx.x;
    int tr = tid & 15;          // n quad
    int tm = tid >> 4;          // m quad
    u64 acc2[8][4];             // [m][n-pair]: 8 m-rows x 4 f32x2 pairs (8 n)
#pragma unroll
    for (int i = 0; i < 8; i++)
#pragma unroll
        for (int p = 0; p < 4; p++) acc2[i][p] = 0ull;

    for (int k0 = 0; k0 < Kd; k0 += 16) {
#pragma unroll
        for (int t = 0; t < 2; t++) {
            int f = tid * 2 + t;
            int rr = f >> 2, kc = (f & 3) * 4;
            float4 v = *(const float4*)&A[(size_t)(m0 + rr) * Kd + k0 + kc];
            As[kc + 0][rr] = v.x; As[kc + 1][rr] = v.y;
            As[kc + 2][rr] = v.z; As[kc + 3][rr] = v.w;
        }
#pragma unroll
        for (int t = 0; t < 2; t++) {
            int f = tid * 2 + t;
            int kk = f >> 5, nc = (f & 31) * 4;
            *(float4*)&Xs[kk][nc] =
                *(const float4*)&Xb[(size_t)(k0 + kk) * NN + n0 + nc];
        }
        __syncthreads();
#pragma unroll
        for (int kk = 0; kk < 16; kk++) {
            float am[8];
            float4 x0 = *(const float4*)&Xs[kk][tr * 4];
            float4 x1 = *(const float4*)&Xs[kk][tr * 4 + 64];
            *(float4*)&am[0] = *(const float4*)&As[kk][tm * 4];
            *(float4*)&am[4] = *(const float4*)&As[kk][tm * 4 + 64];
            u64 xp[4];
            xp[0] = ((const u64*)&x0)[0]; xp[1] = ((const u64*)&x0)[1];
            xp[2] = ((const u64*)&x1)[0]; xp[3] = ((const u64*)&x1)[1];
#pragma unroll
            for (int i = 0; i < 8; i++) {
                u64 ab = bcast2(am[i]);
                fma2(acc2[i][0], ab, xp[0]);
                fma2(acc2[i][1], ab, xp[1]);
                fma2(acc2[i][2], ab, xp[2]);
                fma2(acc2[i][3], ab, xp[3]);
            }
        }
        __syncthreads();
    }
#pragma unroll
    for (int h = 0; h < 2; h++) {
#pragma unroll
        for (int i = 0; i < 4; i++) {
            int m = m0 + tm * 4 + i + h * 64;
            float* orow = Ob + (size_t)m * NN + n0;
            float4 v0, v1;
            ((u64*)&v0)[0] = acc2[h * 4 + i][0]; ((u64*)&v0)[1] = acc2[h * 4 + i][1];
            ((u64*)&v1)[0] = acc2[h * 4 + i][2]; ((u64*)&v1)[1] = acc2[h * 4 + i][3];
            *(float4*)&orow[tr * 4] = v0;
            *(float4*)&orow[tr * 4 + 64] = v1;
        }
    }
}

// ---------------- EdgeConv epilogue v3 (R7 verbatim) ----------------
__global__ void edge_epilogue(const float* __restrict__ UV, const int* __restrict__ idt,
                              float* __restrict__ xcat, int Ch, int rowsPerBatch, int outRow0) {
    int o = blockIdx.x, b = blockIdx.y, tid = threadIdx.x;
    const float* U = UV + ((size_t)b * rowsPerBatch + o) * NPTS;
    const float* V = UV + ((size_t)b * rowsPerBatch + Ch + o) * NPTS;
    const int* it = idt + (size_t)b * KNN * NPTS;
    float* op = xcat + ((size_t)b * 512 + outRow0 + o) * NPTS;

    __shared__ float  sV[NPTS];
    __shared__ float  smax[NPTS];
    __shared__ double sred[256], s2red[256];
    __shared__ float  smu, srstd;

    {
        const float4* V4 = (const float4*)V;
        float4* sV4 = (float4*)sV;
        sV4[tid] = V4[tid];
        sV4[tid + 256] = V4[tid + 256];
        sV4[tid + 512] = V4[tid + 512];
        sV4[tid + 768] = V4[tid + 768];
    }
    __syncthreads();

    double s = 0.0, s2 = 0.0;
    for (int n = tid; n < NPTS / 2; n += 256) {
        int n2 = n + NPTS / 2;
        float ua = U[n], ub = U[n2];
        float ma = -3.4e38f, mb = -3.4e38f;
        float psa = 0.f, pqa = 0.f, psb = 0.f, pqb = 0.f;
#pragma unroll
        for (int kk = 0; kk < KNN; kk++) {
            int ja = it[kk * NPTS + n];
            int jb = it[kk * NPTS + n2];
            float ya = ua + sV[ja];
            float yb = ub + sV[jb];
            ma = fmaxf(ma, ya); psa += ya; pqa += ya * ya;
            mb = fmaxf(mb, yb); psb += yb; pqb += yb * yb;
        }
        smax[n] = ma; smax[n2] = mb;
        s += (double)(psa) + (double)(psb);
        s2 += (double)(pqa) + (double)(pqb);
    }
    sred[tid] = s; s2red[tid] = s2;
    __syncthreads();
    for (int st = 128; st > 0; st >>= 1) {
        if (tid < st) { sred[tid] += sred[tid + st]; s2red[tid] += s2red[tid + st]; }
        __syncthreads();
    }
    if (tid == 0) {
        double cnt = (double)NPTS * KNN;
        double mu  = sred[0] / cnt;
        double var = s2red[0] / cnt - mu * mu;
        smu   = (float)mu;
        srstd = (float)(1.0 / sqrt(var + 1e-5));
    }
    __syncthreads();
    float mu = smu, r = srstd;
    for (int n = tid; n < NPTS; n += 256) {
        float v = (smax[n] - mu) * r;
        op[n] = v >= 0.f ? v : 0.2f * v;
    }
}

// ---------------- final instance-norm (over N) + lrelu ----------------
__global__ void norm_epilogue(const float* __restrict__ Y, float* __restrict__ out) {
    int o = blockIdx.x, b = blockIdx.y, tid = threadIdx.x;
    const float* y = Y + ((size_t)b * CCH + o) * NPTS;
    float* op = out + ((size_t)b * CCH + o) * NPTS;

    __shared__ double sred[256], s2red[256];
    __shared__ float  smu, srstd;

    double s = 0.0, s2 = 0.0;
    for (int n = tid; n < NPTS; n += 256) {
        float v = y[n];
        s += (double)v; s2 += (double)v * (double)v;
    }
    sred[tid] = s; s2red[tid] = s2;
    __syncthreads();
    for (int st = 128; st > 0; st >>= 1) {
        if (tid < st) { sred[tid] += sred[tid + st]; s2red[tid] += s2red[tid + st]; }
        __syncthreads();
    }
    if (tid == 0) {
        double cnt = (double)NPTS;
        double mu  = sred[0] / cnt;
        double var = s2red[0] / cnt - mu * mu;
        smu   = (float)mu;
        srstd = (float)(1.0 / sqrt(var + 1e-5));
    }
    __syncthreads();
    float mu = smu, r = srstd;
    for (int n = tid; n < NPTS; n += 256) {
        float v = (y[n] - mu) * r;
        op[n] = v >= 0.f ? v : 0.2f * v;
    }
}

// ---------------- launch ----------------
extern "C" void kernel_launch(void* const* d_in, const int* in_sizes, int n_in,
                              void* d_out, int out_size) {
    const float* coords = (const float*)d_in[0];
    const float* feats  = (const float*)d_in[1];
    const float* W1     = (const float*)d_in[2];
    const float* W2     = (const float*)d_in[3];
    const float* W3     = (const float*)d_in[4];
    float* out = (float*)d_out;

    float *Wc1, *Wc2, *UV1, *UV2, *xcat, *y3, *kpd;
    int *idt, *kpi;
    cudaGetSymbolAddress((void**)&Wc1,  g_Wc1);
    cudaGetSymbolAddress((void**)&Wc2,  g_Wc2);
    cudaGetSymbolAddress((void**)&UV1,  g_UV1);
    cudaGetSymbolAddress((void**)&UV2,  g_UV2);
    cudaGetSymbolAddress((void**)&xcat, g_xcat);
    cudaGetSymbolAddress((void**)&y3,   g_y3);
    cudaGetSymbolAddress((void**)&idt,  g_idt);
    cudaGetSymbolAddress((void**)&kpd,  g_kpd);
    cudaGetSymbolAddress((void**)&kpi,  g_kpi);

    // L1, L2: prep
    prep_w<<<256, 256>>>(W1, W2, Wc1, Wc2);
    copy_x0<<<(BATCH * CCH * NPTS / 4 + 255) / 256, 256>>>((const float4*)feats, (float4*)xcat);
    // L3: knn_part
    knn_part<<<dim3(NPTS / 256, 4, BATCH), 256>>>(coords, kpd, kpi);
    // L4 (PROFILED SLOT): gemm1 with f32x2
    gemm_kernel<<<dim3(NPTS / 128, 256 / 128, BATCH), 256>>>(
        Wc1, xcat, UV1, 128, (size_t)512 * NPTS, (size_t)256 * NPTS);
    // L5: knn_merge
    knn_merge<<<RTOT / 256, 256>>>(kpd, kpi, idt);
    // L6: edge epilogue stage 1
    edge_epilogue<<<dim3(128, BATCH), 256>>>(UV1, idt, xcat, 128, 256, 128);
    // L7: gemm2
    gemm_kernel<<<dim3(NPTS / 128, 512 / 128, BATCH), 256>>>(
        Wc2, xcat + (size_t)128 * NPTS, UV2, 128, (size_t)512 * NPTS, (size_t)512 * NPTS);
    // L8: edge epilogue stage 2
    edge_epilogue<<<dim3(256, BATCH), 256>>>(UV2, idt, xcat, 256, 512, 256);
    // L9: gemm3
    gemm_kernel<<<dim3(NPTS / 128, 128 / 128, BATCH), 256>>>(
        W3, xcat, y3, 512, (size_t)512 * NPTS, (size_t)128 * NPTS);
    // L10: final norm
    norm_epilogue<<<dim3(128, BATCH), 256>>>(y3, out);
}